// round 11
// baseline (speedup 1.0000x reference)
#include <cuda_runtime.h>
#include <cuda_bf16.h>
#include <cstdint>

// LocalPatternExtractor: reference forward pass is identically zero.
//
// Proof (verified rel_err=0.0 on GB300 in R1):
// quantize_pot_ste clamps mem to <= 127/128 < THRESHOLD=1.0, so the hard
// spike (the forward value of the STE surrogate) is 0 for every element at
// every timestep; acc = 0, out = 0, reg_loss = 0.01*mean(0) = 0. The
// dwconv/pointwise-GEMM/BN stages are dead code in the forward value.
// Optimal kernel = zero-fill of d_out (~82 MB, L2-resident).
//
// R1 profile: one-store-per-thread (20000 one-shot blocks) was block
// launch/retire-churn bound (occ 27%, issue 24%, L2 50.6%, DRAM 19.8%).
// Fix: grid-stride fill, ~12 resident CTAs/SM, ~11 back-to-back STG.128 per
// thread -> store-issue approaches the LTS chip cap (~6300 B/cyc:
// 512B/12cyc per warp-STG.128 x 148 SMs). Predicted ~8us kernel.
// R2-R10: broker timeouts, no data — re-benching the same design unchanged.

__global__ void __launch_bounds__(256) zero_fill_gs(
    float4* __restrict__ out4, size_t n4,
    float* __restrict__ tail, int ntail)
{
    const size_t stride = (size_t)gridDim.x * blockDim.x;
    const float4 z = make_float4(0.f, 0.f, 0.f, 0.f);
    size_t i = (size_t)blockIdx.x * blockDim.x + threadIdx.x;

    // tail first: independent; overlaps with the bulk stores
    if (blockIdx.x == 0 && (int)threadIdx.x < ntail)
        tail[threadIdx.x] = 0.f;

    // unrolled-by-4 strided bulk: back-to-back independent STG.128
    size_t end4 = (n4 > 3 * stride) ? (n4 - 3 * stride) : 0;
    for (; i < end4; i += 4 * stride) {
        out4[i]              = z;
        out4[i +     stride] = z;
        out4[i + 2 * stride] = z;
        out4[i + 3 * stride] = z;
    }
    for (; i < n4; i += stride)
        out4[i] = z;
}

extern "C" void kernel_launch(void* const* d_in, const int* in_sizes, int n_in,
                              void* d_out, int out_size) {
    (void)d_in; (void)in_sizes; (void)n_in;
    float* out = (float*)d_out;
    size_t n  = (size_t)out_size;   // 20,480,001 (16*256*5000 out + reg_loss)
    size_t n4 = n >> 2;
    int ntail = (int)(n & 3);
    float* tail = out + (n4 << 2);

    const int threads = 256;
    const int blocks  = 148 * 12;   // ~12 CTAs/SM resident; grid-stride covers all
    zero_fill_gs<<<blocks, threads>>>((float4*)out, n4, tail, ntail);
}